// round 3
// baseline (speedup 1.0000x reference)
#include <cuda_runtime.h>
#include <math.h>

#define TT 4096   // tokens = 2*2048
#define DD 1024   // d_model
#define FF 4096   // d_ff
#define EE 8      // experts
#define SLOTS (TT*2)

// ---------------- scratch (device globals; allocation-free) ----------------
__device__ float g_hid[(size_t)SLOTS * FF];      // expert hidden, compact rows   (134 MB)
__device__ float g_partial[(size_t)SLOTS * DD];  // weighted expert outputs       (33 MB)
__device__ float g_hid_s[(size_t)TT * FF];       // shared-FFN hidden             (67 MB)
__device__ int   g_perm[SLOTS];                  // slot -> token
__device__ float g_wgt[SLOTS];                   // slot -> gate weight
__device__ int   g_posmap[SLOTS];                // token*2+k -> slot
__device__ int   g_tok_e[SLOTS];
__device__ float g_tok_w[SLOTS];
__device__ int   g_counts[EE];
__device__ int   g_offsets[EE];
__device__ int   g_cursor[EE];

__device__ __forceinline__ float gelu_tanh(float x) {
    float x3 = x * x * x;
    float t = tanhf(0.7978845608028654f * (x + 0.044715f * x3));
    return 0.5f * x * (1.0f + t);
}

// ---------------- init: zero counts, write gate_mean ----------------
__global__ void init_kernel(float* out, int out_size) {
    if (threadIdx.x < EE) g_counts[threadIdx.x] = 0;
    // mean of softmax over its own axis == 1/E exactly
    if (threadIdx.x == 0 && out_size > TT * DD) out[TT * DD] = 0.125f;
}

// ---------------- router: 1 warp per token ----------------
__global__ void router_kernel(const float* __restrict__ h,
                              const float* __restrict__ Wr,
                              const float* __restrict__ br) {
    int warp = (blockIdx.x * blockDim.x + threadIdx.x) >> 5;
    int lane = threadIdx.x & 31;
    if (warp >= TT) return;
    const float* hrow = h + (size_t)warp * DD;
    float s[EE];
#pragma unroll
    for (int e = 0; e < EE; e++) s[e] = 0.f;
    for (int d = lane; d < DD; d += 32) {
        float hv = hrow[d];
        const float4* w4 = (const float4*)(Wr + (size_t)d * EE);
        float4 a = w4[0], b = w4[1];
        s[0] += hv * a.x; s[1] += hv * a.y; s[2] += hv * a.z; s[3] += hv * a.w;
        s[4] += hv * b.x; s[5] += hv * b.y; s[6] += hv * b.z; s[7] += hv * b.w;
    }
#pragma unroll
    for (int e = 0; e < EE; e++)
#pragma unroll
        for (int o = 16; o > 0; o >>= 1) s[e] += __shfl_down_sync(0xffffffffu, s[e], o);
    if (lane == 0) {
        float l[EE];
#pragma unroll
        for (int e = 0; e < EE; e++) l[e] = s[e] + br[e];  // temperature = 1
        float m = l[0];
#pragma unroll
        for (int e = 1; e < EE; e++) m = fmaxf(m, l[e]);
        float p[EE], sum = 0.f;
#pragma unroll
        for (int e = 0; e < EE; e++) { p[e] = expf(l[e] - m); sum += p[e]; }
        int i0 = 0;
#pragma unroll
        for (int e = 1; e < EE; e++) if (l[e] > l[i0]) i0 = e;
        int i1 = -1;
#pragma unroll
        for (int e = 0; e < EE; e++) {
            if (e == i0) continue;
            if (i1 < 0 || l[e] > l[i1]) i1 = e;
        }
        float inv = 1.f / sum;
        g_tok_e[warp * 2 + 0] = i0; g_tok_w[warp * 2 + 0] = p[i0] * inv;
        g_tok_e[warp * 2 + 1] = i1; g_tok_w[warp * 2 + 1] = p[i1] * inv;
        atomicAdd(&g_counts[i0], 1);
        atomicAdd(&g_counts[i1], 1);
    }
}

// ---------------- scan ----------------
__global__ void scan_kernel() {
    if (threadIdx.x == 0) {
        int acc = 0;
        for (int e = 0; e < EE; e++) {
            g_offsets[e] = acc; g_cursor[e] = acc; acc += g_counts[e];
        }
    }
}

// ---------------- scatter ----------------
__global__ void scatter_kernel() {
    int t = blockIdx.x * blockDim.x + threadIdx.x;
    if (t >= TT) return;
#pragma unroll
    for (int k = 0; k < 2; k++) {
        int e = g_tok_e[t * 2 + k];
        int pos = atomicAdd(&g_cursor[e], 1);
        g_perm[pos] = t;
        g_wgt[pos] = g_tok_w[t * 2 + k];
        g_posmap[t * 2 + k] = pos;
    }
}

// ---------------- unified 128x128 SGEMM tile kernel ----------------
// MODE 0: expert GEMM1  (A = gathered h rows,   B = We1[e], out = gelu -> g_hid)
// MODE 1: expert GEMM2  (A = g_hid rows,        B = We2[e], out = w*(.+be2) -> g_partial)
// MODE 2: shared GEMM1  (A = h,                 B = Ws1,    out = gelu -> g_hid_s)
// MODE 3: shared GEMM2  (A = g_hid_s,           B = Ws2,    out = .+bs2+partials -> d_out)
template <int MODE>
__global__ void __launch_bounds__(256, 2)
gemm_tile(const float* __restrict__ Aext, const float* __restrict__ W,
          const float* __restrict__ bias, float* __restrict__ dout) {
    const int Kd = (MODE == 0 || MODE == 2) ? DD : FF;
    const int Nd = (MODE == 0 || MODE == 2) ? FF : DD;
    const int e  = blockIdx.z;
    const int n0 = blockIdx.x * 128;
    const int m0 = blockIdx.y * 128;

    int cnt = 0, base = 0;
    if (MODE <= 1) {
        cnt = g_counts[e];
        base = g_offsets[e];
        if (m0 >= cnt) return;
    }

    const float* Bmat;
    const float* bvec;
    if (MODE == 0)      { Bmat = W + (size_t)e * DD * FF; bvec = bias + (size_t)e * FF; }
    else if (MODE == 1) { Bmat = W + (size_t)e * FF * DD; bvec = bias + (size_t)e * DD; }
    else                { Bmat = W; bvec = bias; }

    __shared__ float As[8][128];
    __shared__ float Bs[8][128];
    __shared__ const float* Ap[128];

    const int tid = threadIdx.x;
    for (int r = tid; r < 128; r += 256) {
        int mr = m0 + r;
        const float* p;
        if (MODE == 0) {
            int mm = (mr < cnt) ? mr : (cnt - 1);
            p = Aext + (size_t)g_perm[base + mm] * DD;
        } else if (MODE == 1) {
            int mm = (mr < cnt) ? mr : (cnt - 1);
            p = g_hid + (size_t)(base + mm) * FF;
        } else if (MODE == 2) {
            p = Aext + (size_t)mr * DD;
        } else {
            p = g_hid_s + (size_t)mr * FF;
        }
        Ap[r] = p;
    }
    __syncthreads();

    const int tx = tid & 15, ty = tid >> 4;
    const int aRow = tid >> 1, aCol = (tid & 1) * 4;
    const int bRow = tid >> 5, bCol = (tid & 31) * 4;

    float c[8][8];
#pragma unroll
    for (int i = 0; i < 8; i++)
#pragma unroll
        for (int j = 0; j < 8; j++) c[i][j] = 0.f;

    for (int kt = 0; kt < Kd; kt += 8) {
        float4 av = *(const float4*)(Ap[aRow] + kt + aCol);
        As[aCol + 0][aRow] = av.x;
        As[aCol + 1][aRow] = av.y;
        As[aCol + 2][aRow] = av.z;
        As[aCol + 3][aRow] = av.w;
        float4 bv = *(const float4*)(Bmat + (size_t)(kt + bRow) * Nd + n0 + bCol);
        *(float4*)&Bs[bRow][bCol] = bv;
        __syncthreads();
#pragma unroll
        for (int k = 0; k < 8; k++) {
            float4 a0 = *(float4*)&As[k][ty * 8];
            float4 a1 = *(float4*)&As[k][ty * 8 + 4];
            float4 b0 = *(float4*)&Bs[k][tx * 8];
            float4 b1 = *(float4*)&Bs[k][tx * 8 + 4];
            float ra[8] = {a0.x, a0.y, a0.z, a0.w, a1.x, a1.y, a1.z, a1.w};
            float rb[8] = {b0.x, b0.y, b0.z, b0.w, b1.x, b1.y, b1.z, b1.w};
#pragma unroll
            for (int i = 0; i < 8; i++)
#pragma unroll
                for (int j = 0; j < 8; j++) c[i][j] = fmaf(ra[i], rb[j], c[i][j]);
        }
        __syncthreads();
    }

#pragma unroll
    for (int i = 0; i < 8; i++) {
        int mr = m0 + ty * 8 + i;
        if (MODE <= 1 && mr >= cnt) continue;
        if (MODE == 0) {
            float* crow = g_hid + (size_t)(base + mr) * FF;
#pragma unroll
            for (int j = 0; j < 8; j++) {
                int n = n0 + tx * 8 + j;
                crow[n] = gelu_tanh(c[i][j] + bvec[n]);
            }
        } else if (MODE == 1) {
            float w = g_wgt[base + mr];
            float* crow = g_partial + (size_t)(base + mr) * DD;
#pragma unroll
            for (int j = 0; j < 8; j++) {
                int n = n0 + tx * 8 + j;
                crow[n] = w * (c[i][j] + bvec[n]);
            }
        } else if (MODE == 2) {
            float* crow = g_hid_s + (size_t)mr * FF;
#pragma unroll
            for (int j = 0; j < 8; j++) {
                int n = n0 + tx * 8 + j;
                crow[n] = gelu_tanh(c[i][j] + bvec[n]);
            }
        } else {
            int p0 = g_posmap[2 * mr], p1 = g_posmap[2 * mr + 1];
            const float* r0 = g_partial + (size_t)p0 * DD;
            const float* r1 = g_partial + (size_t)p1 * DD;
            float* crow = dout + (size_t)mr * DD;
#pragma unroll
            for (int j = 0; j < 8; j++) {
                int n = n0 + tx * 8 + j;
                crow[n] = c[i][j] + bvec[n] + r0[n] + r1[n];
            }
        }
    }
}

// ---------------- launch ----------------
extern "C" void kernel_launch(void* const* d_in, const int* in_sizes, int n_in,
                              void* d_out, int out_size) {
    const float* h   = (const float*)d_in[0];
    const float* Wr  = (const float*)d_in[1];
    const float* br  = (const float*)d_in[2];
    const float* We1 = (const float*)d_in[3];
    const float* be1 = (const float*)d_in[4];
    const float* We2 = (const float*)d_in[5];
    const float* be2 = (const float*)d_in[6];
    const float* Ws1 = (const float*)d_in[7];
    const float* bs1 = (const float*)d_in[8];
    const float* Ws2 = (const float*)d_in[9];
    const float* bs2 = (const float*)d_in[10];
    float* out = (float*)d_out;

    init_kernel<<<1, 32>>>(out, out_size);
    router_kernel<<<TT / 8, 256>>>(h, Wr, br);
    scan_kernel<<<1, 32>>>();
    scatter_kernel<<<TT / 256, 256>>>();
    // expert GEMM1: rows = 2*T slots (per-expert segments), N = FF, K = DD
    gemm_tile<0><<<dim3(FF / 128, TT / 128, EE), 256>>>(h, We1, be1, nullptr);
    // expert GEMM2: N = DD, K = FF
    gemm_tile<1><<<dim3(DD / 128, TT / 128, EE), 256>>>(nullptr, We2, be2, nullptr);
    // shared GEMM1: M = T, N = FF, K = DD
    gemm_tile<2><<<dim3(FF / 128, TT / 128, 1), 256>>>(h, Ws1, bs1, nullptr);
    // shared GEMM2 + combine: M = T, N = DD, K = FF
    gemm_tile<3><<<dim3(DD / 128, TT / 128, 1), 256>>>(nullptr, Ws2, bs2, out);
}